// round 2
// baseline (speedup 1.0000x reference)
#include <cuda_runtime.h>

#define S        128
#define N_LGN    17400
#define N_POST   50000
#define NNZ      800000
#define NBASIS   5
#define OUT_ROW  (N_POST * NBASIS)   // 250000
#define RPB      8                   // rows per block in spmm
#define SCAN_CHUNK 1024
#define SCAN_NBLK  ((N_POST + SCAN_CHUNK - 1) / SCAN_CHUNK)   // 49

// ---------------- device scratch (no allocations allowed) ----------------
__device__ float  g_xT[N_LGN * S];          // transposed input, [c][s]
__device__ int    g_cnt[N_POST];            // per-row edge counts
__device__ int    g_rowptr[N_POST + 1];     // CSR row pointers
__device__ int    g_cursor[N_POST];         // scatter cursors
__device__ int    g_bsum[SCAN_NBLK];        // scan block sums
__device__ int    g_cols[NNZ];              // sorted cols
__device__ float4 g_coef4[NNZ];             // w*f[syn][0..3], sorted
__device__ float  g_coef1[NNZ];             // w*f[syn][4], sorted

// ---------------- 1) transpose x[s][c] -> xT[c][s] ----------------
__global__ void k_transpose(const float* __restrict__ x) {
    __shared__ float tile[32][33];
    int c0 = blockIdx.x * 32;
    int s0 = blockIdx.y * 32;
    #pragma unroll
    for (int j = threadIdx.y; j < 32; j += 8) {
        int c = c0 + threadIdx.x;
        float v = (c < N_LGN) ? x[(s0 + j) * N_LGN + c] : 0.f;
        tile[j][threadIdx.x] = v;
    }
    __syncthreads();
    #pragma unroll
    for (int j = threadIdx.y; j < 32; j += 8) {
        int c = c0 + j;
        if (c < N_LGN) g_xT[c * S + s0 + threadIdx.x] = tile[threadIdx.x][j];
    }
}

// ---------------- 2) counting sort by row ----------------
__global__ void k_zero() {
    int i = blockIdx.x * blockDim.x + threadIdx.x;
    if (i < N_POST) g_cnt[i] = 0;
}

__global__ void k_hist(const int* __restrict__ idx) {
    int e = blockIdx.x * blockDim.x + threadIdx.x;
    if (e < NNZ) atomicAdd(&g_cnt[idx[2 * e]], 1);
}

__global__ void k_scan1() {
    __shared__ int sh[SCAN_CHUNK];
    int i = blockIdx.x * SCAN_CHUNK + threadIdx.x;
    int v = (i < N_POST) ? g_cnt[i] : 0;
    sh[threadIdx.x] = v;
    __syncthreads();
    for (int off = 1; off < SCAN_CHUNK; off <<= 1) {
        int t = (threadIdx.x >= off) ? sh[threadIdx.x - off] : 0;
        __syncthreads();
        sh[threadIdx.x] += t;
        __syncthreads();
    }
    if (i < N_POST) g_rowptr[i] = sh[threadIdx.x] - v;   // exclusive within block
    if (threadIdx.x == SCAN_CHUNK - 1) g_bsum[blockIdx.x] = sh[threadIdx.x];
}

__global__ void k_scan2() {   // <<<1,1>>> serial over 49 block sums
    int acc = 0;
    for (int b = 0; b < SCAN_NBLK; b++) {
        int t = g_bsum[b];
        g_bsum[b] = acc;
        acc += t;
    }
}

__global__ void k_scan3() {
    int i = blockIdx.x * blockDim.x + threadIdx.x;
    if (i < N_POST) {
        int v = g_rowptr[i] + g_bsum[i / SCAN_CHUNK];
        g_rowptr[i] = v;
        g_cursor[i] = v;
    }
    if (i == 0) g_rowptr[N_POST] = NNZ;
}

__global__ void k_scatter(const int* __restrict__ idx,
                          const float* __restrict__ w,
                          const int* __restrict__ sids,
                          const float* __restrict__ synw) {
    int e = blockIdx.x * blockDim.x + threadIdx.x;
    if (e >= NNZ) return;
    int r = idx[2 * e];
    int c = idx[2 * e + 1];
    int p = atomicAdd(&g_cursor[r], 1);
    float wv = w[e];
    int sid = sids[e];
    const float* f = synw + sid * NBASIS;
    g_cols[p]  = c;
    g_coef4[p] = make_float4(wv * f[0], wv * f[1], wv * f[2], wv * f[3]);
    g_coef1[p] = wv * f[4];
}

// ---------------- 3) main SpMM: one warp per row ----------------
__global__ void __launch_bounds__(256) k_spmm(float* __restrict__ out) {
    // staging buffer: sh[s*41 + warp*5 + r]; stride 41 (odd*... 41 mod 32 = 9,
    // odd) makes per-lane store addresses hit 32 distinct banks.
    __shared__ float sh[S * 41];
    int warp = threadIdx.x >> 5;
    int lane = threadIdx.x & 31;
    int n = blockIdx.x * RPB + warp;

    float a[NBASIS][4];
    #pragma unroll
    for (int r = 0; r < NBASIS; r++)
        #pragma unroll
        for (int k = 0; k < 4; k++) a[r][k] = 0.f;

    if (n < N_POST) {
        int beg = g_rowptr[n];
        int end = g_rowptr[n + 1];
        for (int e = beg; e < end; e++) {
            int    c  = __ldg(&g_cols[e]);
            float4 cf = __ldg(&g_coef4[e]);
            float  c4 = __ldg(&g_coef1[e]);
            const float* xp = g_xT + c * S + lane;
            #pragma unroll
            for (int k = 0; k < 4; k++) {
                float xv = __ldg(xp + k * 32);
                a[0][k] = fmaf(xv, cf.x, a[0][k]);
                a[1][k] = fmaf(xv, cf.y, a[1][k]);
                a[2][k] = fmaf(xv, cf.z, a[2][k]);
                a[3][k] = fmaf(xv, cf.w, a[3][k]);
                a[4][k] = fmaf(xv, c4,   a[4][k]);
            }
        }
    }

    #pragma unroll
    for (int k = 0; k < 4; k++) {
        int s = lane + 32 * k;
        int base = s * 41 + warp * NBASIS;
        sh[base + 0] = a[0][k];
        sh[base + 1] = a[1][k];
        sh[base + 2] = a[2][k];
        sh[base + 3] = a[3][k];
        sh[base + 4] = a[4][k];
    }
    __syncthreads();

    // coalesced write-out: per s, RPB*NBASIS = 40 contiguous floats (160B)
    int n0 = blockIdx.x * RPB;
    float* op = out + (size_t)n0 * NBASIS;
    const int TOT = S * RPB * NBASIS;   // 5120
    for (int i = threadIdx.x; i < TOT; i += 256) {
        int s = i / 40;
        int j = i - s * 40;
        op[(size_t)s * OUT_ROW + j] = sh[s * 41 + j];
    }
}

// ---------------- launch ----------------
extern "C" void kernel_launch(void* const* d_in, const int* in_sizes, int n_in,
                              void* d_out, int out_size) {
    const float* inp     = (const float*)d_in[0];
    const int*   indices = (const int*)d_in[1];
    const float* weights = (const float*)d_in[2];
    const float* synw    = (const float*)d_in[3];
    const int*   sids    = (const int*)d_in[4];
    float*       out     = (float*)d_out;
    (void)in_sizes; (void)n_in; (void)out_size;

    dim3 tb(32, 8);
    k_transpose<<<dim3((N_LGN + 31) / 32, S / 32), tb>>>(inp);
    k_zero<<<(N_POST + 255) / 256, 256>>>();
    k_hist<<<(NNZ + 255) / 256, 256>>>(indices);
    k_scan1<<<SCAN_NBLK, SCAN_CHUNK>>>();
    k_scan2<<<1, 1>>>();
    k_scan3<<<(N_POST + 255) / 256, 256>>>();
    k_scatter<<<(NNZ + 255) / 256, 256>>>(indices, weights, sids, synw);
    k_spmm<<<N_POST / RPB, 256>>>(out);
}